// round 2
// baseline (speedup 1.0000x reference)
#include <cuda_runtime.h>
#include <math.h>

#define TCNT 4
#define CH 3
#define HH 128
#define WW 128
#define PSZ 5
#define KSEL 14
#define WSZ 29
#define PADT 16
#define XPH 160
#define XPW 160
#define TX 32
#define TY 8
#define NOFF (WSZ*WSZ)
#define DFEAT 75
#define PLANE (TCNT*HH*WW)

// ---------------- device scratch (no allocations allowed) ----------------
__device__ float  g_mean[TCNT*CH];
__device__ float  g_beta;
__device__ float4 g_xp[TCNT*XPH*XPW];          // normalized, mean-sub, reflect-padded, c in .x/.y/.z
__device__ float  g_pdeno[DFEAT*PLANE];        // plane-major [d][t][H][W]

__device__ __forceinline__ unsigned long long u64min(unsigned long long a, unsigned long long b){return a<b?a:b;}
__device__ __forceinline__ unsigned long long u64max(unsigned long long a, unsigned long long b){return a>b?a:b;}

// ---------------- per (t,c) mean + beta ----------------
__global__ void k_means(const float* __restrict__ noisy, const int* __restrict__ sigp) {
    if (blockIdx.x == 0 && threadIdx.x == 0) {
        unsigned bits = *(const unsigned*)sigp;
        float sv = (bits >> 23) ? __uint_as_float(bits) : (float)(int)bits;
        float sig = sv / 127.5f;
        g_beta = 1.0f / (2.0f * sig * sig * (float)DFEAT);
    }
    int b = blockIdx.x;   // t*3+c
    const float* p = noisy + (size_t)b * (HH*WW);
    float s = 0.f;
    for (int i = threadIdx.x; i < HH*WW; i += 256) s += p[i];
    __shared__ float sm[8];
    #pragma unroll
    for (int off = 16; off; off >>= 1) s += __shfl_down_sync(0xffffffffu, s, off);
    if ((threadIdx.x & 31) == 0) sm[threadIdx.x >> 5] = s;
    __syncthreads();
    if (threadIdx.x == 0) {
        float tot = 0.f;
        #pragma unroll
        for (int i = 0; i < 8; i++) tot += sm[i];
        g_mean[b] = tot * (1.0f/(HH*WW)) * (1.0f/127.5f) - 1.0f;
    }
}

// ---------------- build padded normalized image (float4 per pixel) ----------------
__global__ void k_xp(const float* __restrict__ noisy) {
    int idx = blockIdx.x * 256 + threadIdx.x;       // over t*XPH*XPW
    if (idx >= TCNT*XPH*XPW) return;
    int ix = idx % XPW;
    int r  = idx / XPW;
    int iy = r % XPH;
    int t  = r / XPH;
    int jy = iy - PADT; jy = jy < 0 ? -jy : (jy > HH-1 ? 2*(HH-1)-jy : jy);
    int jx = ix - PADT; jx = jx < 0 ? -jx : (jx > WW-1 ? 2*(WW-1)-jx : jx);
    const float* base = noisy + (size_t)t * CH * HH * WW;
    float4 v;
    v.x = base[(size_t)(0*HH+jy)*WW + jx] * (1.f/127.5f) - 1.f - g_mean[t*3+0];
    v.y = base[(size_t)(1*HH+jy)*WW + jx] * (1.f/127.5f) - 1.f - g_mean[t*3+1];
    v.z = base[(size_t)(2*HH+jy)*WW + jx] * (1.f/127.5f) - 1.f - g_mean[t*3+2];
    v.w = 0.f;
    g_xp[idx] = v;
}

// ---------------- main: distances + top-K + softmax + patch gather ----------------
__global__ void __launch_bounds__(256, 2) k_main() {
    __shared__ float4 reg4[40*64];      // 40KB region: rows ty0..ty0+39, cols tx0..tx0+63
    __shared__ float  e_sm[12*36];
    __shared__ float  h_sm[12*32];

    int t   = blockIdx.z;
    int ty0 = blockIdx.y * TY;
    int tx0 = blockIdx.x * TX;
    int tid = threadIdx.x;

    // stage region
    const float4* xp = g_xp + (size_t)t * XPH * XPW;
    #pragma unroll
    for (int i = tid; i < 40*64; i += 256) {
        int r = i >> 6, c = i & 63;
        reg4[i] = xp[(size_t)(ty0 + r) * XPW + tx0 + c];
    }
    __syncthreads();

    // register-cached query pixels for the e-plane (positions tid and tid+256)
    int er1 = tid / 36, ec1 = tid - er1 * 36;
    int it2 = tid + 256;
    int er2 = it2 / 36, ec2 = it2 - er2 * 36;       // valid when tid < 176
    float4 q1 = reg4[(er1 + 14) * 64 + (ec1 + 14)];
    float4 q2 = (tid < 176) ? reg4[(er2 + 14) * 64 + (ec2 + 14)] : make_float4(0.f,0.f,0.f,0.f);
    int nb1 = er1 * 64 + ec1;
    int nb2 = er2 * 64 + ec2;

    int ly = tid >> 5, lx = tid & 31;
    int hr2 = (tid >> 5) + 8;                       // phase-B second row (tid < 128)

    unsigned long long keys[KSEL];
    #pragma unroll
    for (int i = 0; i < KSEL; i++) keys[i] = 0xFFFFFFFFFFFFFFFFULL;

    int oy = 0, ox = 0;
    for (int off = 0; off < NOFF; off++) {
        int off_lin = oy * 64 + ox;

        // --- A: e plane (12x36) ---
        {
            float4 n = reg4[nb1 + off_lin];
            float a = q1.x - n.x, b = q1.y - n.y, c = q1.z - n.z;
            e_sm[tid] = a*a + b*b + c*c;
            if (tid < 176) {
                float4 n2 = reg4[nb2 + off_lin];
                float a2 = q2.x - n2.x, b2 = q2.y - n2.y, c2 = q2.z - n2.z;
                e_sm[it2] = a2*a2 + b2*b2 + c2*c2;
            }
        }
        __syncthreads();

        // --- B: horizontal 5-sum (12x32) ---
        {
            int r = tid >> 5, x = tid & 31;
            const float* e = e_sm + r * 36 + x;
            h_sm[tid] = e[0] + e[1] + e[2] + e[3] + e[4];
            if (tid < 128) {
                const float* e2 = e_sm + hr2 * 36 + x;
                h_sm[tid + 256] = e2[0] + e2[1] + e2[2] + e2[3] + e2[4];
            }
        }
        __syncthreads();

        // --- C: vertical 5-sum + top-K insert ---
        {
            const float* h = h_sm + ly * 32 + lx;
            float d = h[0] + h[32] + h[64] + h[96] + h[128];
            unsigned long long key =
                ((unsigned long long)__float_as_uint(d) << 32) | (unsigned)off;
            if (__any_sync(0xffffffffu, key < keys[KSEL-1])) {
                #pragma unroll
                for (int i = KSEL-1; i >= 1; i--)
                    keys[i] = u64min(keys[i], u64max(keys[i-1], key));
                keys[0] = u64min(keys[0], key);
            }
        }
        __syncthreads();   // protect e_sm/h_sm reuse next iteration

        ox++; if (ox == WSZ) { ox = 0; oy++; }
    }

    // --- softmax over exact distances ---
    float w[KSEL];
    int   olin[KSEL];
    float beta = g_beta;
    float d0 = __uint_as_float((unsigned)(keys[0] >> 32));
    float ssum = 0.f;
    #pragma unroll
    for (int i = 0; i < KSEL; i++) {
        float di = __uint_as_float((unsigned)(keys[i] >> 32));
        float wi = expf(beta * (d0 - di));
        w[i] = wi; ssum += wi;
        int o  = (int)(keys[i] & 0xFFFFFFFFULL);
        int oyk = o / WSZ;
        int oxk = o - oyk * WSZ;
        olin[i] = oyk * 64 + oxk;
    }
    float inv = 1.0f / ssum;
    #pragma unroll
    for (int i = 0; i < KSEL; i++) w[i] *= inv;

    // --- weighted patch gather from smem region, plane-major write ---
    float* pd = g_pdeno + ((size_t)t * HH + (ty0 + ly)) * WW + (tx0 + lx);
    int base_px = ly * 64 + lx;
    #pragma unroll
    for (int dy = 0; dy < PSZ; dy++) {
        #pragma unroll
        for (int dx = 0; dx < PSZ; dx++) {
            float ax = 0.f, ay = 0.f, az = 0.f;
            int bb = base_px + dy * 64 + dx;
            #pragma unroll
            for (int k = 0; k < KSEL; k++) {
                float4 v = reg4[bb + olin[k]];
                ax += w[k] * v.x;
                ay += w[k] * v.y;
                az += w[k] * v.z;
            }
            int p = (dy * PSZ + dx) * 3;
            pd[(size_t)(p + 0) * PLANE] = ax;
            pd[(size_t)(p + 1) * PLANE] = ay;
            pd[(size_t)(p + 2) * PLANE] = az;
        }
    }
}

// ---------------- fold + denormalize ----------------
__global__ void k_fold(float* __restrict__ out) {
    int idx = blockIdx.x * 256 + threadIdx.x;        // over t*c*H*W
    if (idx >= TCNT*CH*HH*WW) return;
    int x = idx & 127;
    int r = idx >> 7;
    int y = r & 127;
    r >>= 7;
    int c = r % 3;
    int t = r / 3;
    float s = 0.f;
    int n = 0;
    #pragma unroll
    for (int py = 0; py < PSZ; py++) {
        int yy = y + 2 - py;
        if (yy < 0 || yy > HH-1) continue;
        #pragma unroll
        for (int px = 0; px < PSZ; px++) {
            int xx = x + 2 - px;
            if (xx < 0 || xx > WW-1) continue;
            int p = (py * PSZ + px) * 3 + c;
            s += g_pdeno[(size_t)p * PLANE + ((size_t)t * HH + yy) * WW + xx];
            n++;
        }
    }
    out[idx] = 127.5f * (s / (float)n + g_mean[t*3+c] + 1.0f);
}

// ---------------- launch ----------------
extern "C" void kernel_launch(void* const* d_in, const int* in_sizes, int n_in,
                              void* d_out, int out_size) {
    const float* noisy = (const float*)d_in[0];
    const int*   sigp  = (const int*)d_in[1];
    float*       out   = (float*)d_out;

    k_means<<<TCNT*CH, 256>>>(noisy, sigp);
    k_xp<<<(TCNT*XPH*XPW + 255)/256, 256>>>(noisy);
    dim3 grid(WW/TX, HH/TY, TCNT);
    k_main<<<grid, 256>>>();
    k_fold<<<(TCNT*CH*HH*WW + 255)/256, 256>>>(out);
}